// round 11
// baseline (speedup 1.0000x reference)
#include <cuda_runtime.h>
#include <cuda_bf16.h>
#include <cstdint>

#define Bb 2
#define Nn 2048
#define Ee 1024
#define Hh 16
#define Dd 64
#define BH (Bb*Hh)
#define ROWS (Bb*Nn)

// ---------------------------------------------------------------------------
// Scratch — ONLY ever referenced from device code (never passed as kernel args)
// ---------------------------------------------------------------------------
__device__ __nv_bfloat16 g_xh[ROWS * Ee];      // x split
__device__ __nv_bfloat16 g_xl[ROWS * Ee];
__device__ __nv_bfloat16 g_Qh[BH * Nn * Dd];   // [B,H,N,D], pre-scaled by 1/8
__device__ __nv_bfloat16 g_Ql[BH * Nn * Dd];
__device__ __nv_bfloat16 g_Kh[BH * Nn * Dd];
__device__ __nv_bfloat16 g_Kl[BH * Nn * Dd];
__device__ __nv_bfloat16 g_Vth[BH * Dd * Nn];  // [B,H,D,N] (transposed)
__device__ __nv_bfloat16 g_Vtl[BH * Dd * Nn];
__device__ __nv_bfloat16 g_ctx_h[ROWS * Ee];   // attention out split, [B,N,E]
__device__ __nv_bfloat16 g_ctx_l[ROWS * Ee];
__device__ __nv_bfloat16 g_wqkvT_h[3 * Ee * Ee];  // [3E][E] (n-major)
__device__ __nv_bfloat16 g_wqkvT_l[3 * Ee * Ee];
__device__ __nv_bfloat16 g_wprojT_h[Ee * Ee];
__device__ __nv_bfloat16 g_wprojT_l[Ee * Ee];

// ---------------------------------------------------------------------------
// helpers
// ---------------------------------------------------------------------------
__device__ __forceinline__ uint32_t smem_u32(const void* p) {
    uint32_t a;
    asm("{ .reg .u64 t; cvta.to.shared.u64 t, %1; cvt.u32.u64 %0, t; }" : "=r"(a) : "l"(p));
    return a;
}
#define CP16(dst_u32, src_ptr) \
    asm volatile("cp.async.cg.shared.global [%0], [%1], 16;" :: "r"(dst_u32), "l"(src_ptr))
#define CP_COMMIT() asm volatile("cp.async.commit_group;" ::: "memory")
#define CP_WAIT1()  asm volatile("cp.async.wait_group 1;" ::: "memory")
#define CP_WAIT0()  asm volatile("cp.async.wait_group 0;" ::: "memory")

__device__ __forceinline__ void mma_bf16(float* c, const uint32_t* a, const uint32_t* b) {
    asm volatile(
        "mma.sync.aligned.m16n8k16.row.col.f32.bf16.bf16.f32 "
        "{%0,%1,%2,%3}, {%4,%5,%6,%7}, {%8,%9}, {%0,%1,%2,%3};"
        : "+f"(c[0]), "+f"(c[1]), "+f"(c[2]), "+f"(c[3])
        : "r"(a[0]), "r"(a[1]), "r"(a[2]), "r"(a[3]), "r"(b[0]), "r"(b[1]));
}

__device__ __forceinline__ float fexp(float x) {
    float y = fmaxf(x * 1.4426950408889634f, -120.f);
    float n = floorf(y);
    float f = y - n;
    float p = 1.5403530451e-4f;
    p = fmaf(p, f, 1.3333558146e-3f);
    p = fmaf(p, f, 9.6181291076e-3f);
    p = fmaf(p, f, 5.5504108664e-2f);
    p = fmaf(p, f, 2.4022650695e-1f);
    p = fmaf(p, f, 6.9314718056e-1f);
    p = fmaf(p, f, 1.0f);
    return __int_as_float(__float_as_int(p) + (((int)n) << 23));
}

__device__ __forceinline__ void split2(float x, float y, uint32_t& hi, uint32_t& lo) {
    __nv_bfloat16 hx = __float2bfloat16(x);
    __nv_bfloat16 hy = __float2bfloat16(y);
    __nv_bfloat162 hv(hx, hy);
    __nv_bfloat162 lv(__float2bfloat16(x - __bfloat162float(hx)),
                      __float2bfloat16(y - __bfloat162float(hy)));
    hi = *(uint32_t*)&hv;
    lo = *(uint32_t*)&lv;
}

// ---------------------------------------------------------------------------
// x -> bf16 hi/lo split (device-ref destinations)
// ---------------------------------------------------------------------------
__global__ __launch_bounds__(256)
void conv_x_kernel(const float* __restrict__ X) {
    const int i = (blockIdx.x * 256 + threadIdx.x) * 4;
    const float4 v = *(const float4*)&X[i];
    const float vv[4] = {v.x, v.y, v.z, v.w};
    __nv_bfloat16 h[4], l[4];
    #pragma unroll
    for (int j = 0; j < 4; ++j) {
        h[j] = __float2bfloat16(vv[j]);
        l[j] = __float2bfloat16(vv[j] - __bfloat162float(h[j]));
    }
    *(uint2*)&g_xh[i] = *(uint2*)h;
    *(uint2*)&g_xl[i] = *(uint2*)l;
}

// ---------------------------------------------------------------------------
// Transpose + split W[1024, NW] -> device-global WT hi/lo [NW][1024]
// ---------------------------------------------------------------------------
template<int NW, int MODE>
__global__ __launch_bounds__(256)
void conv_wT_kernel(const float* __restrict__ W) {
    __nv_bfloat16* Th = (MODE == 0) ? g_wqkvT_h : g_wprojT_h;
    __nv_bfloat16* Tl = (MODE == 0) ? g_wqkvT_l : g_wprojT_l;
    __shared__ float ts[32][33];
    const int tx = threadIdx.x & 31;
    const int ty = threadIdx.x >> 5;
    const int nb = blockIdx.x * 32;
    const int kb = blockIdx.y * 32;
    #pragma unroll
    for (int i = 0; i < 32; i += 8)
        ts[ty + i][tx] = W[(size_t)(kb + ty + i) * NW + nb + tx];
    __syncthreads();
    #pragma unroll
    for (int i = 0; i < 32; i += 8) {
        const float v = ts[tx][ty + i];
        const __nv_bfloat16 h = __float2bfloat16(v);
        Th[(size_t)(nb + ty + i) * Ee + kb + tx] = h;
        Tl[(size_t)(nb + ty + i) * Ee + kb + tx] = __float2bfloat16(v - __bfloat162float(h));
    }
}

// ---------------------------------------------------------------------------
// HMMA GEMM — all-bf16 inputs, cp.async 2-stage double buffer.
// C[4096, NW] = A @ WT^T (+bias); AhBh + AhBl + AlBh, fp32 accum.
// BM=BN=128, BK=16, 256 thr, 48 KB static smem, padded-24 layout (proven).
// MODE 0: A = g_xh/g_xl, epilogue -> Qh/Ql(x0.125), Kh/Kl, Vth/Vtl
// MODE 1: A = g_ctx_h/g_ctx_l, epilogue -> fp32 Cout (+bias)
// ---------------------------------------------------------------------------
template<int NW, int MODE>
__global__ __launch_bounds__(256)
void hmma_gemm(const float* __restrict__ bias, float* __restrict__ Cout)
{
    __shared__ __nv_bfloat16 Ah[2][128][24], Al[2][128][24];
    __shared__ __nv_bfloat16 Bh[2][128][24], Bl[2][128][24];   // [n][k]

    const int tid  = threadIdx.x;
    const int lane = tid & 31;
    const int wid  = tid >> 5;
    const int gid  = lane >> 2;
    const int tig  = lane & 3;
    const int wm   = wid & 1;
    const int wn   = wid >> 1;

    const int m0 = blockIdx.y * 128;
    const int n0 = blockIdx.x * 128;

    const __nv_bfloat16* Ash = (MODE == 0) ? g_xh : g_ctx_h;
    const __nv_bfloat16* Asl = (MODE == 0) ? g_xl : g_ctx_l;
    const __nv_bfloat16* WTh = (MODE == 0) ? g_wqkvT_h : g_wprojT_h;
    const __nv_bfloat16* WTl = (MODE == 0) ? g_wqkvT_l : g_wprojT_l;

    const int a_row = tid >> 1;          // 0..127
    const int a_k   = (tid & 1) * 8;     // 0 or 8

    const size_t a_goff = (size_t)(m0 + a_row) * Ee + a_k;
    const size_t b_goff = (size_t)(n0 + a_row) * Ee + a_k;

    float acc[4][4][4] = {};

    auto issue = [&](int c) {
        const int k0 = c * 16;
        const int buf = c & 1;
        CP16(smem_u32(&Ah[buf][a_row][a_k]), Ash + a_goff + k0);
        CP16(smem_u32(&Al[buf][a_row][a_k]), Asl + a_goff + k0);
        CP16(smem_u32(&Bh[buf][a_row][a_k]), WTh + b_goff + k0);
        CP16(smem_u32(&Bl[buf][a_row][a_k]), WTl + b_goff + k0);
        CP_COMMIT();
    };

    issue(0);

    #pragma unroll 1
    for (int c = 0; c < 64; ++c) {
        if (c < 63) { issue(c + 1); CP_WAIT1(); }
        else        { CP_WAIT0(); }
        __syncthreads();

        const int buf = c & 1;
        uint32_t af[4][4], bhf[4][2], blf[4][2];
        #pragma unroll
        for (int mt = 0; mt < 4; ++mt) {
            const int r = wm * 64 + mt * 16 + gid;
            af[mt][0] = *(const uint32_t*)&Ah[buf][r][2 * tig];
            af[mt][1] = *(const uint32_t*)&Ah[buf][r + 8][2 * tig];
            af[mt][2] = *(const uint32_t*)&Ah[buf][r][2 * tig + 8];
            af[mt][3] = *(const uint32_t*)&Ah[buf][r + 8][2 * tig + 8];
        }
        #pragma unroll
        for (int nt = 0; nt < 4; ++nt) {
            const int rn = wn * 32 + nt * 8 + gid;
            bhf[nt][0] = *(const uint32_t*)&Bh[buf][rn][2 * tig];
            bhf[nt][1] = *(const uint32_t*)&Bh[buf][rn][2 * tig + 8];
            blf[nt][0] = *(const uint32_t*)&Bl[buf][rn][2 * tig];
            blf[nt][1] = *(const uint32_t*)&Bl[buf][rn][2 * tig + 8];
        }
        #pragma unroll
        for (int mt = 0; mt < 4; ++mt)
            #pragma unroll
            for (int nt = 0; nt < 4; ++nt)
                mma_bf16(acc[mt][nt], af[mt], bhf[nt]);
        #pragma unroll
        for (int mt = 0; mt < 4; ++mt)
            #pragma unroll
            for (int nt = 0; nt < 4; ++nt)
                mma_bf16(acc[mt][nt], af[mt], blf[nt]);
        #pragma unroll
        for (int mt = 0; mt < 4; ++mt) {
            const int r = wm * 64 + mt * 16 + gid;
            af[mt][0] = *(const uint32_t*)&Al[buf][r][2 * tig];
            af[mt][1] = *(const uint32_t*)&Al[buf][r + 8][2 * tig];
            af[mt][2] = *(const uint32_t*)&Al[buf][r][2 * tig + 8];
            af[mt][3] = *(const uint32_t*)&Al[buf][r + 8][2 * tig + 8];
        }
        #pragma unroll
        for (int mt = 0; mt < 4; ++mt)
            #pragma unroll
            for (int nt = 0; nt < 4; ++nt)
                mma_bf16(acc[mt][nt], af[mt], bhf[nt]);

        __syncthreads();   // compute done before next issue overwrites this buf
    }

    // ---- epilogue (R9/R10-proven) ----
    #pragma unroll
    for (int mt = 0; mt < 4; ++mt) {
        #pragma unroll
        for (int hrow = 0; hrow < 2; ++hrow) {
            const int m = m0 + wm * 64 + mt * 16 + hrow * 8 + gid;
            #pragma unroll
            for (int nt = 0; nt < 4; ++nt) {
                const int c0 = n0 + wn * 32 + nt * 8 + tig * 2;
                const float r0 = acc[mt][nt][hrow * 2 + 0] + bias[c0];
                const float r1 = acc[mt][nt][hrow * 2 + 1] + bias[c0 + 1];
                if (MODE == 0) {
                    const int sel = c0 >> 10;
                    const int rem = c0 & 1023;
                    const int hh  = rem >> 6;
                    const int d0  = rem & 63;
                    const int b   = m >> 11;
                    const int n   = m & 2047;
                    if (sel == 2) {
                        const size_t vidx = ((size_t)(b * Hh + hh) * Dd + d0) * Nn + n;
                        const __nv_bfloat16 h0 = __float2bfloat16(r0);
                        const __nv_bfloat16 h1 = __float2bfloat16(r1);
                        g_Vth[vidx]      = h0;
                        g_Vtl[vidx]      = __float2bfloat16(r0 - __bfloat162float(h0));
                        g_Vth[vidx + Nn] = h1;
                        g_Vtl[vidx + Nn] = __float2bfloat16(r1 - __bfloat162float(h1));
                    } else {
                        const size_t idx = ((size_t)(b * Hh + hh) * Nn + n) * Dd + d0;
                        const float s0 = (sel == 0) ? r0 * 0.125f : r0;
                        const float s1 = (sel == 0) ? r1 * 0.125f : r1;
                        uint32_t hi, lo;
                        split2(s0, s1, hi, lo);
                        __nv_bfloat16* dh = (sel == 0) ? g_Qh : g_Kh;
                        __nv_bfloat16* dl = (sel == 0) ? g_Ql : g_Kl;
                        *(uint32_t*)&dh[idx] = hi;
                        *(uint32_t*)&dl[idx] = lo;
                    }
                } else {
                    float2 o = {r0, r1};
                    *(float2*)&Cout[(size_t)m * NW + c0] = o;
                }
            }
        }
    }
}

// ---------------------------------------------------------------------------
// HMMA flash attention — R10-proven mainloop (351us); epilogue now emits
// bf16 hi/lo ctx (R6-proven) for the bf16 proj GEMM.
// grid (Nn/64, BH), 128 threads.
// ---------------------------------------------------------------------------
__global__ __launch_bounds__(128)
void attn_kernel()
{
    __shared__ __nv_bfloat16 Ksh[64][72], Ksl[64][72];
    __shared__ __nv_bfloat16 Vsh[64][72], Vsl[64][72];

    const int tid  = threadIdx.x;
    const int lane = tid & 31;
    const int w    = tid >> 5;            // 0..3
    const int gid  = lane >> 2;
    const int tig  = lane & 3;

    const int bh    = blockIdx.y;
    const int qrow0 = blockIdx.x * 64 + w * 16;

    const __nv_bfloat16* Qhp = g_Qh + ((size_t)bh * Nn + qrow0) * Dd;
    const __nv_bfloat16* Qlp = g_Ql + ((size_t)bh * Nn + qrow0) * Dd;
    const __nv_bfloat16* Khg = g_Kh + (size_t)bh * Nn * Dd;
    const __nv_bfloat16* Klg = g_Kl + (size_t)bh * Nn * Dd;
    const __nv_bfloat16* Vhg = g_Vth + (size_t)bh * Dd * Nn;
    const __nv_bfloat16* Vlg = g_Vtl + (size_t)bh * Dd * Nn;

    uint32_t qh[4][4], ql[4][4];
    #pragma unroll
    for (int kc = 0; kc < 4; ++kc) {
        const int d0 = kc * 16 + 2 * tig;
        qh[kc][0] = *(const uint32_t*)&Qhp[(size_t)gid * Dd + d0];
        qh[kc][1] = *(const uint32_t*)&Qhp[(size_t)(gid + 8) * Dd + d0];
        qh[kc][2] = *(const uint32_t*)&Qhp[(size_t)gid * Dd + d0 + 8];
        qh[kc][3] = *(const uint32_t*)&Qhp[(size_t)(gid + 8) * Dd + d0 + 8];
        ql[kc][0] = *(const uint32_t*)&Qlp[(size_t)gid * Dd + d0];
        ql[kc][1] = *(const uint32_t*)&Qlp[(size_t)(gid + 8) * Dd + d0];
        ql[kc][2] = *(const uint32_t*)&Qlp[(size_t)gid * Dd + d0 + 8];
        ql[kc][3] = *(const uint32_t*)&Qlp[(size_t)(gid + 8) * Dd + d0 + 8];
    }

    float o[8][4];
    #pragma unroll
    for (int j = 0; j < 8; ++j)
        #pragma unroll
        for (int k = 0; k < 4; ++k)
            o[j][k] = 0.f;
    float m0 = -1e30f, m1 = -1e30f, l0 = 0.f, l1 = 0.f;

    const int ld_r  = tid >> 3;           // 0..15
    const int ld_c  = (tid & 7) * 8;      // 0..56

    #pragma unroll 1
    for (int t0 = 0; t0 < Nn; t0 += 64) {
        __syncthreads();
        #pragma unroll
        for (int i = 0; i < 4; ++i) {
            const int r = ld_r + i * 16;
            *(uint4*)&Ksh[r][ld_c] = *(const uint4*)&Khg[(size_t)(t0 + r) * Dd + ld_c];
            *(uint4*)&Ksl[r][ld_c] = *(const uint4*)&Klg[(size_t)(t0 + r) * Dd + ld_c];
            *(uint4*)&Vsh[r][ld_c] = *(const uint4*)&Vhg[(size_t)r * Nn + t0 + ld_c];
            *(uint4*)&Vsl[r][ld_c] = *(const uint4*)&Vlg[(size_t)r * Nn + t0 + ld_c];
        }
        __syncthreads();

        float s[8][4];
        #pragma unroll
        for (int j = 0; j < 8; ++j)
            #pragma unroll
            for (int k = 0; k < 4; ++k)
                s[j][k] = 0.f;
        #pragma unroll
        for (int j = 0; j < 8; ++j) {
            const int rn = j * 8 + gid;
            #pragma unroll
            for (int kc = 0; kc < 4; ++kc) {
                const int kk = kc * 16 + 2 * tig;
                uint32_t bhv[2], blv[2];
                bhv[0] = *(const uint32_t*)&Ksh[rn][kk];
                bhv[1] = *(const uint32_t*)&Ksh[rn][kk + 8];
                blv[0] = *(const uint32_t*)&Ksl[rn][kk];
                blv[1] = *(const uint32_t*)&Ksl[rn][kk + 8];
                mma_bf16(s[j], qh[kc], bhv);
                mma_bf16(s[j], qh[kc], blv);
                mma_bf16(s[j], ql[kc], bhv);
            }
        }

        float mloc0 = -1e30f, mloc1 = -1e30f;
        #pragma unroll
        for (int j = 0; j < 8; ++j) {
            mloc0 = fmaxf(mloc0, fmaxf(s[j][0], s[j][1]));
            mloc1 = fmaxf(mloc1, fmaxf(s[j][2], s[j][3]));
        }
        mloc0 = fmaxf(mloc0, __shfl_xor_sync(0xffffffffu, mloc0, 1));
        mloc0 = fmaxf(mloc0, __shfl_xor_sync(0xffffffffu, mloc0, 2));
        mloc1 = fmaxf(mloc1, __shfl_xor_sync(0xffffffffu, mloc1, 1));
        mloc1 = fmaxf(mloc1, __shfl_xor_sync(0xffffffffu, mloc1, 2));
        const float mnew0 = fmaxf(m0, mloc0);
        const float mnew1 = fmaxf(m1, mloc1);
        const float corr0 = fexp(m0 - mnew0);
        const float corr1 = fexp(m1 - mnew1);
        #pragma unroll
        for (int j = 0; j < 8; ++j) {
            o[j][0] *= corr0; o[j][1] *= corr0;
            o[j][2] *= corr1; o[j][3] *= corr1;
        }
        float ls0 = 0.f, ls1 = 0.f;
        #pragma unroll
        for (int j = 0; j < 8; ++j) {
            s[j][0] = fexp(s[j][0] - mnew0);
            s[j][1] = fexp(s[j][1] - mnew0);
            s[j][2] = fexp(s[j][2] - mnew1);
            s[j][3] = fexp(s[j][3] - mnew1);
            ls0 += s[j][0] + s[j][1];
            ls1 += s[j][2] + s[j][3];
        }
        ls0 += __shfl_xor_sync(0xffffffffu, ls0, 1);
        ls0 += __shfl_xor_sync(0xffffffffu, ls0, 2);
        ls1 += __shfl_xor_sync(0xffffffffu, ls1, 1);
        ls1 += __shfl_xor_sync(0xffffffffu, ls1, 2);
        l0 = l0 * corr0 + ls0;
        l1 = l1 * corr1 + ls1;
        m0 = mnew0; m1 = mnew1;

        uint32_t ph[4][4], pl[4][4];
        #pragma unroll
        for (int kc = 0; kc < 4; ++kc) {
            split2(s[2 * kc][0],     s[2 * kc][1],     ph[kc][0], pl[kc][0]);
            split2(s[2 * kc][2],     s[2 * kc][3],     ph[kc][1], pl[kc][1]);
            split2(s[2 * kc + 1][0], s[2 * kc + 1][1], ph[kc][2], pl[kc][2]);
            split2(s[2 * kc + 1][2], s[2 * kc + 1][3], ph[kc][3], pl[kc][3]);
        }

        #pragma unroll
        for (int j = 0; j < 8; ++j) {
            const int rn = j * 8 + gid;
            #pragma unroll
            for (int kc = 0; kc < 4; ++kc) {
                const int kk = kc * 16 + 2 * tig;
                uint32_t bhv[2], blv[2];
                bhv[0] = *(const uint32_t*)&Vsh[rn][kk];
                bhv[1] = *(const uint32_t*)&Vsh[rn][kk + 8];
                blv[0] = *(const uint32_t*)&Vsl[rn][kk];
                blv[1] = *(const uint32_t*)&Vsl[rn][kk + 8];
                mma_bf16(o[j], ph[kc], bhv);
                mma_bf16(o[j], ph[kc], blv);
                mma_bf16(o[j], pl[kc], bhv);
            }
        }
    }

    // ---- write ctx bf16 hi/lo [B,N,E] (R6-proven epilogue form) ----
    const float inv0 = 1.f / l0;
    const float inv1 = 1.f / l1;
    const int b  = bh >> 4;
    const int hh = bh & 15;
    const int row0 = qrow0 + gid;
    #pragma unroll
    for (int j = 0; j < 8; ++j) {
        const int col = hh * Dd + j * 8 + 2 * tig;
        uint32_t hi0, lo0, hi1, lo1;
        split2(o[j][0] * inv0, o[j][1] * inv0, hi0, lo0);
        split2(o[j][2] * inv1, o[j][3] * inv1, hi1, lo1);
        const size_t i0 = (size_t)(b * Nn + row0) * Ee + col;
        const size_t i1 = (size_t)(b * Nn + row0 + 8) * Ee + col;
        *(uint32_t*)&g_ctx_h[i0] = hi0;
        *(uint32_t*)&g_ctx_l[i0] = lo0;
        *(uint32_t*)&g_ctx_h[i1] = hi1;
        *(uint32_t*)&g_ctx_l[i1] = lo1;
    }
}

// ---------------------------------------------------------------------------
extern "C" void kernel_launch(void* const* d_in, const int* in_sizes, int n_in,
                              void* d_out, int out_size)
{
    const float* x      = (const float*)d_in[0];
    const float* w_qkv  = (const float*)d_in[1];
    const float* b_qkv  = (const float*)d_in[2];
    const float* w_proj = (const float*)d_in[3];
    const float* b_proj = (const float*)d_in[4];
    float* out = (float*)d_out;

    conv_x_kernel<<<ROWS * Ee / 4 / 256, 256>>>(x);
    conv_wT_kernel<3 * Ee, 0><<<dim3(3 * Ee / 32, Ee / 32), 256>>>(w_qkv);
    conv_wT_kernel<Ee, 1><<<dim3(Ee / 32, Ee / 32), 256>>>(w_proj);
    hmma_gemm<3 * Ee, 0><<<dim3(3 * Ee / 128, ROWS / 128), 256>>>(b_qkv, nullptr);
    attn_kernel<<<dim3(Nn / 64, BH), 128>>>();
    hmma_gemm<Ee, 1><<<dim3(Ee / 128, ROWS / 128), 256>>>(b_proj, out);
}

// round 12
// speedup vs baseline: 1.0584x; 1.0584x over previous
#include <cuda_runtime.h>
#include <cuda_bf16.h>
#include <cstdint>

#define Bb 2
#define Nn 2048
#define Ee 1024
#define Hh 16
#define Dd 64
#define BH (Bb*Hh)
#define ROWS (Bb*Nn)
#define TK 32   // attention kv tile

// ---------------------------------------------------------------------------
// Scratch — ONLY ever referenced from device code (never passed as kernel args)
// ---------------------------------------------------------------------------
__device__ __nv_bfloat16 g_Qh[BH * Nn * Dd];   // [B,H,N,D], pre-scaled by 1/8
__device__ __nv_bfloat16 g_Ql[BH * Nn * Dd];
__device__ __nv_bfloat16 g_Kh[BH * Nn * Dd];
__device__ __nv_bfloat16 g_Kl[BH * Nn * Dd];
__device__ __nv_bfloat16 g_Vth[BH * Dd * Nn];  // [B,H,D,N] (transposed)
__device__ __nv_bfloat16 g_Vtl[BH * Dd * Nn];
__device__ float g_ctx[ROWS * Ee];             // attention out, [B,N,E] fp32
__device__ __nv_bfloat16 g_wqkvT_h[3 * Ee * Ee];  // [3E][E] (n-major)
__device__ __nv_bfloat16 g_wqkvT_l[3 * Ee * Ee];
__device__ __nv_bfloat16 g_wprojT_h[Ee * Ee];
__device__ __nv_bfloat16 g_wprojT_l[Ee * Ee];

// ---------------------------------------------------------------------------
// helpers
// ---------------------------------------------------------------------------
__device__ __forceinline__ uint32_t smem_u32(const void* p) {
    uint32_t a;
    asm("{ .reg .u64 t; cvta.to.shared.u64 t, %1; cvt.u32.u64 %0, t; }" : "=r"(a) : "l"(p));
    return a;
}
#define CP16(dst_u32, src_ptr) \
    asm volatile("cp.async.cg.shared.global [%0], [%1], 16;" :: "r"(dst_u32), "l"(src_ptr))
#define CP_COMMIT() asm volatile("cp.async.commit_group;" ::: "memory")
#define CP_WAIT1()  asm volatile("cp.async.wait_group 1;" ::: "memory")
#define CP_WAIT0()  asm volatile("cp.async.wait_group 0;" ::: "memory")

__device__ __forceinline__ void mma_bf16(float* c, const uint32_t* a, const uint32_t* b) {
    asm volatile(
        "mma.sync.aligned.m16n8k16.row.col.f32.bf16.bf16.f32 "
        "{%0,%1,%2,%3}, {%4,%5,%6,%7}, {%8,%9}, {%0,%1,%2,%3};"
        : "+f"(c[0]), "+f"(c[1]), "+f"(c[2]), "+f"(c[3])
        : "r"(a[0]), "r"(a[1]), "r"(a[2]), "r"(a[3]), "r"(b[0]), "r"(b[1]));
}

__device__ __forceinline__ float fexp(float x) {
    float y = fmaxf(x * 1.4426950408889634f, -120.f);
    float n = floorf(y);
    float f = y - n;
    float p = 1.5403530451e-4f;
    p = fmaf(p, f, 1.3333558146e-3f);
    p = fmaf(p, f, 9.6181291076e-3f);
    p = fmaf(p, f, 5.5504108664e-2f);
    p = fmaf(p, f, 2.4022650695e-1f);
    p = fmaf(p, f, 6.9314718056e-1f);
    p = fmaf(p, f, 1.0f);
    return __int_as_float(__float_as_int(p) + (((int)n) << 23));
}

__device__ __forceinline__ void split2(float x, float y, uint32_t& hi, uint32_t& lo) {
    __nv_bfloat16 hx = __float2bfloat16(x);
    __nv_bfloat16 hy = __float2bfloat16(y);
    __nv_bfloat162 hv(hx, hy);
    __nv_bfloat162 lv(__float2bfloat16(x - __bfloat162float(hx)),
                      __float2bfloat16(y - __bfloat162float(hy)));
    hi = *(uint32_t*)&hv;
    lo = *(uint32_t*)&lv;
}

// ---------------------------------------------------------------------------
// Transpose + split W[1024, NW] -> device-global WT hi/lo [NW][1024] (R10-proven)
// ---------------------------------------------------------------------------
template<int NW, int MODE>
__global__ __launch_bounds__(256)
void conv_wT_kernel(const float* __restrict__ W) {
    __nv_bfloat16* Th = (MODE == 0) ? g_wqkvT_h : g_wprojT_h;
    __nv_bfloat16* Tl = (MODE == 0) ? g_wqkvT_l : g_wprojT_l;
    __shared__ float ts[32][33];
    const int tx = threadIdx.x & 31;
    const int ty = threadIdx.x >> 5;
    const int nb = blockIdx.x * 32;
    const int kb = blockIdx.y * 32;
    #pragma unroll
    for (int i = 0; i < 32; i += 8)
        ts[ty + i][tx] = W[(size_t)(kb + ty + i) * NW + nb + tx];
    __syncthreads();
    #pragma unroll
    for (int i = 0; i < 32; i += 8) {
        const float v = ts[tx][ty + i];
        const __nv_bfloat16 h = __float2bfloat16(v);
        Th[(size_t)(nb + ty + i) * Ee + kb + tx] = h;
        Tl[(size_t)(nb + ty + i) * Ee + kb + tx] = __float2bfloat16(v - __bfloat162float(h));
    }
}

// ---------------------------------------------------------------------------
// HMMA GEMM (R10-proven, verbatim)
// ---------------------------------------------------------------------------
template<int NW, int MODE>
__global__ __launch_bounds__(256)
void hmma_gemm(const float* __restrict__ Ain,
               const float* __restrict__ bias, float* __restrict__ Cout)
{
    __shared__ __nv_bfloat16 Ah[128][24], Al[128][24];
    __shared__ __nv_bfloat16 Bh[128][24], Bl[128][24];   // [n][k]

    const int tid  = threadIdx.x;
    const int lane = tid & 31;
    const int wid  = tid >> 5;
    const int gid  = lane >> 2;
    const int tig  = lane & 3;
    const int wm   = wid & 1;
    const int wn   = wid >> 1;

    const int m0 = blockIdx.y * 128;
    const int n0 = blockIdx.x * 128;

    const float* A = (MODE == 0) ? Ain : g_ctx;
    const __nv_bfloat16* WTh = (MODE == 0) ? g_wqkvT_h : g_wprojT_h;
    const __nv_bfloat16* WTl = (MODE == 0) ? g_wqkvT_l : g_wprojT_l;

    const int a_row = tid >> 1;
    const int a_k   = (tid & 1) * 8;

    float acc[4][4][4] = {};

    #pragma unroll 1
    for (int c = 0; c < 64; ++c) {
        const int k0 = c * 16;
        const float4 pa0 = *(const float4*)&A[(size_t)(m0 + a_row) * Ee + k0 + a_k];
        const float4 pa1 = *(const float4*)&A[(size_t)(m0 + a_row) * Ee + k0 + a_k + 4];
        const uint4  pbh = *(const uint4*)&WTh[(size_t)(n0 + a_row) * Ee + k0 + a_k];
        const uint4  pbl = *(const uint4*)&WTl[(size_t)(n0 + a_row) * Ee + k0 + a_k];

        __syncthreads();

        {
            const float va[8] = {pa0.x, pa0.y, pa0.z, pa0.w, pa1.x, pa1.y, pa1.z, pa1.w};
            __nv_bfloat16 h[8], l[8];
            #pragma unroll
            for (int j = 0; j < 8; ++j) {
                h[j] = __float2bfloat16(va[j]);
                l[j] = __float2bfloat16(va[j] - __bfloat162float(h[j]));
            }
            *(uint4*)&Ah[a_row][a_k] = *(uint4*)h;
            *(uint4*)&Al[a_row][a_k] = *(uint4*)l;
            *(uint4*)&Bh[a_row][a_k] = pbh;
            *(uint4*)&Bl[a_row][a_k] = pbl;
        }
        __syncthreads();

        uint32_t af[4][4], bhf[4][2], blf[4][2];
        #pragma unroll
        for (int mt = 0; mt < 4; ++mt) {
            const int r = wm * 64 + mt * 16 + gid;
            af[mt][0] = *(const uint32_t*)&Ah[r][2 * tig];
            af[mt][1] = *(const uint32_t*)&Ah[r + 8][2 * tig];
            af[mt][2] = *(const uint32_t*)&Ah[r][2 * tig + 8];
            af[mt][3] = *(const uint32_t*)&Ah[r + 8][2 * tig + 8];
        }
        #pragma unroll
        for (int nt = 0; nt < 4; ++nt) {
            const int rn = wn * 32 + nt * 8 + gid;
            bhf[nt][0] = *(const uint32_t*)&Bh[rn][2 * tig];
            bhf[nt][1] = *(const uint32_t*)&Bh[rn][2 * tig + 8];
            blf[nt][0] = *(const uint32_t*)&Bl[rn][2 * tig];
            blf[nt][1] = *(const uint32_t*)&Bl[rn][2 * tig + 8];
        }
        #pragma unroll
        for (int mt = 0; mt < 4; ++mt)
            #pragma unroll
            for (int nt = 0; nt < 4; ++nt)
                mma_bf16(acc[mt][nt], af[mt], bhf[nt]);
        #pragma unroll
        for (int mt = 0; mt < 4; ++mt)
            #pragma unroll
            for (int nt = 0; nt < 4; ++nt)
                mma_bf16(acc[mt][nt], af[mt], blf[nt]);
        #pragma unroll
        for (int mt = 0; mt < 4; ++mt) {
            const int r = wm * 64 + mt * 16 + gid;
            af[mt][0] = *(const uint32_t*)&Al[r][2 * tig];
            af[mt][1] = *(const uint32_t*)&Al[r + 8][2 * tig];
            af[mt][2] = *(const uint32_t*)&Al[r][2 * tig + 8];
            af[mt][3] = *(const uint32_t*)&Al[r + 8][2 * tig + 8];
        }
        #pragma unroll
        for (int mt = 0; mt < 4; ++mt)
            #pragma unroll
            for (int nt = 0; nt < 4; ++nt)
                mma_bf16(acc[mt][nt], af[mt], bhf[nt]);
    }

    #pragma unroll
    for (int mt = 0; mt < 4; ++mt) {
        #pragma unroll
        for (int hrow = 0; hrow < 2; ++hrow) {
            const int m = m0 + wm * 64 + mt * 16 + hrow * 8 + gid;
            #pragma unroll
            for (int nt = 0; nt < 4; ++nt) {
                const int c0 = n0 + wn * 32 + nt * 8 + tig * 2;
                const float r0 = acc[mt][nt][hrow * 2 + 0] + bias[c0];
                const float r1 = acc[mt][nt][hrow * 2 + 1] + bias[c0 + 1];
                if (MODE == 0) {
                    const int sel = c0 >> 10;
                    const int rem = c0 & 1023;
                    const int hh  = rem >> 6;
                    const int d0  = rem & 63;
                    const int b   = m >> 11;
                    const int n   = m & 2047;
                    if (sel == 2) {
                        const size_t vidx = ((size_t)(b * Hh + hh) * Dd + d0) * Nn + n;
                        const __nv_bfloat16 h0 = __float2bfloat16(r0);
                        const __nv_bfloat16 h1 = __float2bfloat16(r1);
                        g_Vth[vidx]      = h0;
                        g_Vtl[vidx]      = __float2bfloat16(r0 - __bfloat162float(h0));
                        g_Vth[vidx + Nn] = h1;
                        g_Vtl[vidx + Nn] = __float2bfloat16(r1 - __bfloat162float(h1));
                    } else {
                        const size_t idx = ((size_t)(b * Hh + hh) * Nn + n) * Dd + d0;
                        const float s0 = (sel == 0) ? r0 * 0.125f : r0;
                        const float s1 = (sel == 0) ? r1 * 0.125f : r1;
                        uint32_t hi, lo;
                        split2(s0, s1, hi, lo);
                        __nv_bfloat16* dh = (sel == 0) ? g_Qh : g_Kh;
                        __nv_bfloat16* dl = (sel == 0) ? g_Ql : g_Kl;
                        *(uint32_t*)&dh[idx] = hi;
                        *(uint32_t*)&dl[idx] = lo;
                    }
                } else {
                    float2 o = {r0, r1};
                    *(float2*)&Cout[(size_t)m * NW + c0] = o;
                }
            }
        }
    }
}

// ---------------------------------------------------------------------------
// HMMA flash attention — R10 math, cp.async double-buffered KV tiles of 32.
// grid (Nn/64, BH), 128 threads. Static smem ~38 KB (2 buffers).
// ---------------------------------------------------------------------------
__global__ __launch_bounds__(128)
void attn_kernel()
{
    __shared__ __nv_bfloat16 Ksh[2][TK][72], Ksl[2][TK][72];   // [kv][d]
    __shared__ __nv_bfloat16 Vsh[2][Dd][40], Vsl[2][Dd][40];   // [d][kv]

    const int tid  = threadIdx.x;
    const int lane = tid & 31;
    const int w    = tid >> 5;            // 0..3
    const int gid  = lane >> 2;
    const int tig  = lane & 3;

    const int bh    = blockIdx.y;
    const int qrow0 = blockIdx.x * 64 + w * 16;

    const __nv_bfloat16* Qhp = g_Qh + ((size_t)bh * Nn + qrow0) * Dd;
    const __nv_bfloat16* Qlp = g_Ql + ((size_t)bh * Nn + qrow0) * Dd;
    const __nv_bfloat16* Khg = g_Kh + (size_t)bh * Nn * Dd;
    const __nv_bfloat16* Klg = g_Kl + (size_t)bh * Nn * Dd;
    const __nv_bfloat16* Vhg = g_Vth + (size_t)bh * Dd * Nn;
    const __nv_bfloat16* Vlg = g_Vtl + (size_t)bh * Dd * Nn;

    uint32_t qh[4][4], ql[4][4];
    #pragma unroll
    for (int kc = 0; kc < 4; ++kc) {
        const int d0 = kc * 16 + 2 * tig;
        qh[kc][0] = *(const uint32_t*)&Qhp[(size_t)gid * Dd + d0];
        qh[kc][1] = *(const uint32_t*)&Qhp[(size_t)(gid + 8) * Dd + d0];
        qh[kc][2] = *(const uint32_t*)&Qhp[(size_t)gid * Dd + d0 + 8];
        qh[kc][3] = *(const uint32_t*)&Qhp[(size_t)(gid + 8) * Dd + d0 + 8];
        ql[kc][0] = *(const uint32_t*)&Qlp[(size_t)gid * Dd + d0];
        ql[kc][1] = *(const uint32_t*)&Qlp[(size_t)(gid + 8) * Dd + d0];
        ql[kc][2] = *(const uint32_t*)&Qlp[(size_t)gid * Dd + d0 + 8];
        ql[kc][3] = *(const uint32_t*)&Qlp[(size_t)(gid + 8) * Dd + d0 + 8];
    }

    float o[8][4];
    #pragma unroll
    for (int j = 0; j < 8; ++j)
        #pragma unroll
        for (int k = 0; k < 4; ++k)
            o[j][k] = 0.f;
    float m0 = -1e30f, m1 = -1e30f, l0 = 0.f, l1 = 0.f;

    // load indices: K tile 32x64 (8 16B-chunks/row), V tile 64x32 (4/row)
    const int k_r = tid >> 3;             // 0..15
    const int k_c = (tid & 7) * 8;        // 0..56
    const int v_r = tid >> 2;             // 0..31
    const int v_c = (tid & 3) * 8;        // 0..24

    auto issue = [&](int t) {
        const int t0 = t * TK;
        const int buf = t & 1;
        #pragma unroll
        for (int i = 0; i < 2; ++i) {
            const int r = k_r + i * 16;
            CP16(smem_u32(&Ksh[buf][r][k_c]), Khg + (size_t)(t0 + r) * Dd + k_c);
            CP16(smem_u32(&Ksl[buf][r][k_c]), Klg + (size_t)(t0 + r) * Dd + k_c);
        }
        #pragma unroll
        for (int i = 0; i < 2; ++i) {
            const int r = v_r + i * 32;
            CP16(smem_u32(&Vsh[buf][r][v_c]), Vhg + (size_t)r * Nn + t0 + v_c);
            CP16(smem_u32(&Vsl[buf][r][v_c]), Vlg + (size_t)r * Nn + t0 + v_c);
        }
        CP_COMMIT();
    };

    issue(0);

    #pragma unroll 1
    for (int t = 0; t < Nn / TK; ++t) {
        if (t < Nn / TK - 1) { issue(t + 1); CP_WAIT1(); }
        else                 { CP_WAIT0(); }
        __syncthreads();
        const int buf = t & 1;

        // ---- S = Q K^T on this 32-kv tile (3 passes) ----
        float s[4][4];
        #pragma unroll
        for (int j = 0; j < 4; ++j)
            #pragma unroll
            for (int k = 0; k < 4; ++k)
                s[j][k] = 0.f;
        #pragma unroll
        for (int j = 0; j < 4; ++j) {
            const int rn = j * 8 + gid;
            #pragma unroll
            for (int kc = 0; kc < 4; ++kc) {
                const int kk = kc * 16 + 2 * tig;
                uint32_t bhv[2], blv[2];
                bhv[0] = *(const uint32_t*)&Ksh[buf][rn][kk];
                bhv[1] = *(const uint32_t*)&Ksh[buf][rn][kk + 8];
                blv[0] = *(const uint32_t*)&Ksl[buf][rn][kk];
                blv[1] = *(const uint32_t*)&Ksl[buf][rn][kk + 8];
                mma_bf16(s[j], qh[kc], bhv);
                mma_bf16(s[j], qh[kc], blv);
                mma_bf16(s[j], ql[kc], bhv);
            }
        }

        // ---- online softmax ----
        float mloc0 = -1e30f, mloc1 = -1e30f;
        #pragma unroll
        for (int j = 0; j < 4; ++j) {
            mloc0 = fmaxf(mloc0, fmaxf(s[j][0], s[j][1]));
            mloc1 = fmaxf(mloc1, fmaxf(s[j][2], s[j][3]));
        }
        mloc0 = fmaxf(mloc0, __shfl_xor_sync(0xffffffffu, mloc0, 1));
        mloc0 = fmaxf(mloc0, __shfl_xor_sync(0xffffffffu, mloc0, 2));
        mloc1 = fmaxf(mloc1, __shfl_xor_sync(0xffffffffu, mloc1, 1));
        mloc1 = fmaxf(mloc1, __shfl_xor_sync(0xffffffffu, mloc1, 2));
        const float mnew0 = fmaxf(m0, mloc0);
        const float mnew1 = fmaxf(m1, mloc1);
        const float corr0 = fexp(m0 - mnew0);
        const float corr1 = fexp(m1 - mnew1);
        #pragma unroll
        for (int j = 0; j < 8; ++j) {
            o[j][0] *= corr0; o[j][1] *= corr0;
            o[j][2] *= corr1; o[j][3] *= corr1;
        }
        float ls0 = 0.f, ls1 = 0.f;
        #pragma unroll
        for (int j = 0; j < 4; ++j) {
            s[j][0] = fexp(s[j][0] - mnew0);
            s[j][1] = fexp(s[j][1] - mnew0);
            s[j][2] = fexp(s[j][2] - mnew1);
            s[j][3] = fexp(s[j][3] - mnew1);
            ls0 += s[j][0] + s[j][1];
            ls1 += s[j][2] + s[j][3];
        }
        ls0 += __shfl_xor_sync(0xffffffffu, ls0, 1);
        ls0 += __shfl_xor_sync(0xffffffffu, ls0, 2);
        ls1 += __shfl_xor_sync(0xffffffffu, ls1, 1);
        ls1 += __shfl_xor_sync(0xffffffffu, ls1, 2);
        l0 = l0 * corr0 + ls0;
        l1 = l1 * corr1 + ls1;
        m0 = mnew0; m1 = mnew1;

        // ---- P -> bf16 hi/lo A-fragments (kv = 32 -> 2 kc chunks) ----
        uint32_t ph[2][4], pl[2][4];
        #pragma unroll
        for (int kc = 0; kc < 2; ++kc) {
            split2(s[2 * kc][0],     s[2 * kc][1],     ph[kc][0], pl[kc][0]);
            split2(s[2 * kc][2],     s[2 * kc][3],     ph[kc][1], pl[kc][1]);
            split2(s[2 * kc + 1][0], s[2 * kc + 1][1], ph[kc][2], pl[kc][2]);
            split2(s[2 * kc + 1][2], s[2 * kc + 1][3], ph[kc][3], pl[kc][3]);
        }

        // ---- O += P V (3 passes) ----
        #pragma unroll
        for (int j = 0; j < 8; ++j) {
            const int rn = j * 8 + gid;       // d index
            #pragma unroll
            for (int kc = 0; kc < 2; ++kc) {
                const int kk = kc * 16 + 2 * tig;
                uint32_t bhv[2], blv[2];
                bhv[0] = *(const uint32_t*)&Vsh[buf][rn][kk];
                bhv[1] = *(const uint32_t*)&Vsh[buf][rn][kk + 8];
                blv[0] = *(const uint32_t*)&Vsl[buf][rn][kk];
                blv[1] = *(const uint32_t*)&Vsl[buf][rn][kk + 8];
                mma_bf16(o[j], ph[kc], bhv);
                mma_bf16(o[j], ph[kc], blv);
                mma_bf16(o[j], pl[kc], bhv);
            }
        }
        __syncthreads();   // compute done before issue(t+2) overwrites this buf
    }

    // ---- write ctx [B,N,E] fp32 (R10-proven) ----
    const float inv0 = 1.f / l0;
    const float inv1 = 1.f / l1;
    const int b  = bh >> 4;
    const int hh = bh & 15;
    const int row0 = qrow0 + gid;
    #pragma unroll
    for (int j = 0; j < 8; ++j) {
        const int col = hh * Dd + j * 8 + 2 * tig;
        float2 o0 = {o[j][0] * inv0, o[j][1] * inv0};
        float2 o1 = {o[j][2] * inv1, o[j][3] * inv1};
        *(float2*)&g_ctx[(size_t)(b * Nn + row0) * Ee + col] = o0;
        *(float2*)&g_ctx[(size_t)(b * Nn + row0 + 8) * Ee + col] = o1;
    }
}

// ---------------------------------------------------------------------------
extern "C" void kernel_launch(void* const* d_in, const int* in_sizes, int n_in,
                              void* d_out, int out_size)
{
    const float* x      = (const float*)d_in[0];
    const float* w_qkv  = (const float*)d_in[1];
    const float* b_qkv  = (const float*)d_in[2];
    const float* w_proj = (const float*)d_in[3];
    const float* b_proj = (const float*)d_in[4];
    float* out = (float*)d_out;

    conv_wT_kernel<3 * Ee, 0><<<dim3(3 * Ee / 32, Ee / 32), 256>>>(w_qkv);
    conv_wT_kernel<Ee, 1><<<dim3(Ee / 32, Ee / 32), 256>>>(w_proj);
    hmma_gemm<3 * Ee, 0><<<dim3(3 * Ee / 128, ROWS / 128), 256>>>(x, b_qkv, nullptr);
    attn_kernel<<<dim3(Nn / 64, BH), 128>>>();
    hmma_gemm<Ee, 1><<<dim3(Ee / 128, ROWS / 128), 256>>>(nullptr, b_proj, out);
}

// round 13
// speedup vs baseline: 1.0606x; 1.0021x over previous
#include <cuda_runtime.h>
#include <cuda_bf16.h>
#include <cstdint>

#define Bb 2
#define Nn 2048
#define Ee 1024
#define Hh 16
#define Dd 64
#define BH (Bb*Hh)
#define ROWS (Bb*Nn)

// ---------------------------------------------------------------------------
// Scratch — ONLY ever referenced from device code (never passed as kernel args)
// ---------------------------------------------------------------------------
__device__ __nv_bfloat16 g_Qh[BH * Nn * Dd];   // [B,H,N,D], pre-scaled by 1/8
__device__ __nv_bfloat16 g_Ql[BH * Nn * Dd];
__device__ __nv_bfloat16 g_Kh[BH * Nn * Dd];
__device__ __nv_bfloat16 g_Kl[BH * Nn * Dd];
__device__ __nv_bfloat16 g_Vth[BH * Dd * Nn];  // [B,H,D,N] (transposed)
__device__ __nv_bfloat16 g_Vtl[BH * Dd * Nn];
__device__ float g_ctx[ROWS * Ee];             // attention out, [B,N,E] fp32
__device__ __nv_bfloat16 g_wqkvT_h[3 * Ee * Ee];  // [3E][E] (n-major)
__device__ __nv_bfloat16 g_wqkvT_l[3 * Ee * Ee];
__device__ __nv_bfloat16 g_wprojT_h[Ee * Ee];
__device__ __nv_bfloat16 g_wprojT_l[Ee * Ee];

// ---------------------------------------------------------------------------
// helpers
// ---------------------------------------------------------------------------
__device__ __forceinline__ uint32_t smem_u32(const void* p) {
    uint32_t a;
    asm("{ .reg .u64 t; cvta.to.shared.u64 t, %1; cvt.u32.u64 %0, t; }" : "=r"(a) : "l"(p));
    return a;
}

__device__ __forceinline__ void mma_bf16(float* c, const uint32_t* a, const uint32_t* b) {
    asm volatile(
        "mma.sync.aligned.m16n8k16.row.col.f32.bf16.bf16.f32 "
        "{%0,%1,%2,%3}, {%4,%5,%6,%7}, {%8,%9}, {%0,%1,%2,%3};"
        : "+f"(c[0]), "+f"(c[1]), "+f"(c[2]), "+f"(c[3])
        : "r"(a[0]), "r"(a[1]), "r"(a[2]), "r"(a[3]), "r"(b[0]), "r"(b[1]));
}

#define LDMX4(r, addr) \
    asm volatile("ldmatrix.sync.aligned.m8n8.x4.shared.b16 {%0,%1,%2,%3}, [%4];" \
        : "=r"((r)[0]), "=r"((r)[1]), "=r"((r)[2]), "=r"((r)[3]) : "r"(addr))

// fast split: packed bf16x2 hi + residual lo (6 instrs)
__device__ __forceinline__ void split2(float x, float y, uint32_t& hi, uint32_t& lo) {
    __nv_bfloat162 h2 = __float22bfloat162_rn(make_float2(x, y));
    hi = *(uint32_t*)&h2;
    const float hx = __uint_as_float(hi << 16);
    const float hy = __uint_as_float(hi & 0xffff0000u);
    __nv_bfloat162 l2 = __float22bfloat162_rn(make_float2(x - hx, y - hy));
    lo = *(uint32_t*)&l2;
}

// ---------------------------------------------------------------------------
// Transpose + split W[1024, NW] -> device-global WT hi/lo [NW][1024] (R10-proven)
// ---------------------------------------------------------------------------
template<int NW, int MODE>
__global__ __launch_bounds__(256)
void conv_wT_kernel(const float* __restrict__ W) {
    __nv_bfloat16* Th = (MODE == 0) ? g_wqkvT_h : g_wprojT_h;
    __nv_bfloat16* Tl = (MODE == 0) ? g_wqkvT_l : g_wprojT_l;
    __shared__ float ts[32][33];
    const int tx = threadIdx.x & 31;
    const int ty = threadIdx.x >> 5;
    const int nb = blockIdx.x * 32;
    const int kb = blockIdx.y * 32;
    #pragma unroll
    for (int i = 0; i < 32; i += 8)
        ts[ty + i][tx] = W[(size_t)(kb + ty + i) * NW + nb + tx];
    __syncthreads();
    #pragma unroll
    for (int i = 0; i < 32; i += 8) {
        const float v = ts[tx][ty + i];
        const __nv_bfloat16 h = __float2bfloat16(v);
        Th[(size_t)(nb + ty + i) * Ee + kb + tx] = h;
        Tl[(size_t)(nb + ty + i) * Ee + kb + tx] = __float2bfloat16(v - __bfloat162float(h));
    }
}

// ---------------------------------------------------------------------------
// HMMA GEMM (R10-proven, verbatim)
// ---------------------------------------------------------------------------
template<int NW, int MODE>
__global__ __launch_bounds__(256)
void hmma_gemm(const float* __restrict__ Ain,
               const float* __restrict__ bias, float* __restrict__ Cout)
{
    __shared__ __nv_bfloat16 Ah[128][24], Al[128][24];
    __shared__ __nv_bfloat16 Bh[128][24], Bl[128][24];   // [n][k]

    const int tid  = threadIdx.x;
    const int lane = tid & 31;
    const int wid  = tid >> 5;
    const int gid  = lane >> 2;
    const int tig  = lane & 3;
    const int wm   = wid & 1;
    const int wn   = wid >> 1;

    const int m0 = blockIdx.y * 128;
    const int n0 = blockIdx.x * 128;

    const float* A = (MODE == 0) ? Ain : g_ctx;
    const __nv_bfloat16* WTh = (MODE == 0) ? g_wqkvT_h : g_wprojT_h;
    const __nv_bfloat16* WTl = (MODE == 0) ? g_wqkvT_l : g_wprojT_l;

    const int a_row = tid >> 1;
    const int a_k   = (tid & 1) * 8;

    float acc[4][4][4] = {};

    #pragma unroll 1
    for (int c = 0; c < 64; ++c) {
        const int k0 = c * 16;
        const float4 pa0 = *(const float4*)&A[(size_t)(m0 + a_row) * Ee + k0 + a_k];
        const float4 pa1 = *(const float4*)&A[(size_t)(m0 + a_row) * Ee + k0 + a_k + 4];
        const uint4  pbh = *(const uint4*)&WTh[(size_t)(n0 + a_row) * Ee + k0 + a_k];
        const uint4  pbl = *(const uint4*)&WTl[(size_t)(n0 + a_row) * Ee + k0 + a_k];

        __syncthreads();

        {
            const float va[8] = {pa0.x, pa0.y, pa0.z, pa0.w, pa1.x, pa1.y, pa1.z, pa1.w};
            __nv_bfloat16 h[8], l[8];
            #pragma unroll
            for (int j = 0; j < 8; ++j) {
                h[j] = __float2bfloat16(va[j]);
                l[j] = __float2bfloat16(va[j] - __bfloat162float(h[j]));
            }
            *(uint4*)&Ah[a_row][a_k] = *(uint4*)h;
            *(uint4*)&Al[a_row][a_k] = *(uint4*)l;
            *(uint4*)&Bh[a_row][a_k] = pbh;
            *(uint4*)&Bl[a_row][a_k] = pbl;
        }
        __syncthreads();

        uint32_t af[4][4], bhf[4][2], blf[4][2];
        #pragma unroll
        for (int mt = 0; mt < 4; ++mt) {
            const int r = wm * 64 + mt * 16 + gid;
            af[mt][0] = *(const uint32_t*)&Ah[r][2 * tig];
            af[mt][1] = *(const uint32_t*)&Ah[r + 8][2 * tig];
            af[mt][2] = *(const uint32_t*)&Ah[r][2 * tig + 8];
            af[mt][3] = *(const uint32_t*)&Ah[r + 8][2 * tig + 8];
        }
        #pragma unroll
        for (int nt = 0; nt < 4; ++nt) {
            const int rn = wn * 32 + nt * 8 + gid;
            bhf[nt][0] = *(const uint32_t*)&Bh[rn][2 * tig];
            bhf[nt][1] = *(const uint32_t*)&Bh[rn][2 * tig + 8];
            blf[nt][0] = *(const uint32_t*)&Bl[rn][2 * tig];
            blf[nt][1] = *(const uint32_t*)&Bl[rn][2 * tig + 8];
        }
        #pragma unroll
        for (int mt = 0; mt < 4; ++mt)
            #pragma unroll
            for (int nt = 0; nt < 4; ++nt)
                mma_bf16(acc[mt][nt], af[mt], bhf[nt]);
        #pragma unroll
        for (int mt = 0; mt < 4; ++mt)
            #pragma unroll
            for (int nt = 0; nt < 4; ++nt)
                mma_bf16(acc[mt][nt], af[mt], blf[nt]);
        #pragma unroll
        for (int mt = 0; mt < 4; ++mt) {
            const int r = wm * 64 + mt * 16 + gid;
            af[mt][0] = *(const uint32_t*)&Al[r][2 * tig];
            af[mt][1] = *(const uint32_t*)&Al[r + 8][2 * tig];
            af[mt][2] = *(const uint32_t*)&Al[r][2 * tig + 8];
            af[mt][3] = *(const uint32_t*)&Al[r + 8][2 * tig + 8];
        }
        #pragma unroll
        for (int mt = 0; mt < 4; ++mt)
            #pragma unroll
            for (int nt = 0; nt < 4; ++nt)
                mma_bf16(acc[mt][nt], af[mt], bhf[nt]);
    }

    #pragma unroll
    for (int mt = 0; mt < 4; ++mt) {
        #pragma unroll
        for (int hrow = 0; hrow < 2; ++hrow) {
            const int m = m0 + wm * 64 + mt * 16 + hrow * 8 + gid;
            #pragma unroll
            for (int nt = 0; nt < 4; ++nt) {
                const int c0 = n0 + wn * 32 + nt * 8 + tig * 2;
                const float r0 = acc[mt][nt][hrow * 2 + 0] + bias[c0];
                const float r1 = acc[mt][nt][hrow * 2 + 1] + bias[c0 + 1];
                if (MODE == 0) {
                    const int sel = c0 >> 10;
                    const int rem = c0 & 1023;
                    const int hh  = rem >> 6;
                    const int d0  = rem & 63;
                    const int b   = m >> 11;
                    const int n   = m & 2047;
                    if (sel == 2) {
                        const size_t vidx = ((size_t)(b * Hh + hh) * Dd + d0) * Nn + n;
                        const __nv_bfloat16 h0 = __float2bfloat16(r0);
                        const __nv_bfloat16 h1 = __float2bfloat16(r1);
                        g_Vth[vidx]      = h0;
                        g_Vtl[vidx]      = __float2bfloat16(r0 - __bfloat162float(h0));
                        g_Vth[vidx + Nn] = h1;
                        g_Vtl[vidx + Nn] = __float2bfloat16(r1 - __bfloat162float(h1));
                    } else {
                        const size_t idx = ((size_t)(b * Hh + hh) * Nn + n) * Dd + d0;
                        const float s0 = (sel == 0) ? r0 * 0.125f : r0;
                        const float s1 = (sel == 0) ? r1 * 0.125f : r1;
                        uint32_t hi, lo;
                        split2(s0, s1, hi, lo);
                        __nv_bfloat16* dh = (sel == 0) ? g_Qh : g_Kh;
                        __nv_bfloat16* dl = (sel == 0) ? g_Ql : g_Kl;
                        *(uint32_t*)&dh[idx] = hi;
                        *(uint32_t*)&dl[idx] = lo;
                    }
                } else {
                    float2 o = {r0, r1};
                    *(float2*)&Cout[(size_t)m * NW + c0] = o;
                }
            }
        }
    }
}

// ---------------------------------------------------------------------------
// HMMA flash attention — R10 structure (64-kv tiles, 128 thr, 351us) with:
//   * ldmatrix.x4 for K/V fragment loads (256 LDS -> 64 ldmatrix)
//   * __expf (MUFU) instead of FMA-chain exp
//   * fast split2
// grid (Nn/64, BH), 128 threads.
// ---------------------------------------------------------------------------
__global__ __launch_bounds__(128)
void attn_kernel()
{
    __shared__ __nv_bfloat16 Ksh[64][72], Ksl[64][72];
    __shared__ __nv_bfloat16 Vsh[64][72], Vsl[64][72];   // [d][kv]

    const int tid  = threadIdx.x;
    const int lane = tid & 31;
    const int w    = tid >> 5;            // 0..3
    const int gid  = lane >> 2;
    const int tig  = lane & 3;

    const int bh    = blockIdx.y;
    const int qrow0 = blockIdx.x * 64 + w * 16;

    const __nv_bfloat16* Qhp = g_Qh + ((size_t)bh * Nn + qrow0) * Dd;
    const __nv_bfloat16* Qlp = g_Ql + ((size_t)bh * Nn + qrow0) * Dd;
    const __nv_bfloat16* Khg = g_Kh + (size_t)bh * Nn * Dd;
    const __nv_bfloat16* Klg = g_Kl + (size_t)bh * Nn * Dd;
    const __nv_bfloat16* Vhg = g_Vth + (size_t)bh * Dd * Nn;
    const __nv_bfloat16* Vlg = g_Vtl + (size_t)bh * Dd * Nn;

    uint32_t qh[4][4], ql[4][4];
    #pragma unroll
    for (int kc = 0; kc < 4; ++kc) {
        const int d0 = kc * 16 + 2 * tig;
        qh[kc][0] = *(const uint32_t*)&Qhp[(size_t)gid * Dd + d0];
        qh[kc][1] = *(const uint32_t*)&Qhp[(size_t)(gid + 8) * Dd + d0];
        qh[kc][2] = *(const uint32_t*)&Qhp[(size_t)gid * Dd + d0 + 8];
        qh[kc][3] = *(const uint32_t*)&Qhp[(size_t)(gid + 8) * Dd + d0 + 8];
        ql[kc][0] = *(const uint32_t*)&Qlp[(size_t)gid * Dd + d0];
        ql[kc][1] = *(const uint32_t*)&Qlp[(size_t)(gid + 8) * Dd + d0];
        ql[kc][2] = *(const uint32_t*)&Qlp[(size_t)gid * Dd + d0 + 8];
        ql[kc][3] = *(const uint32_t*)&Qlp[(size_t)(gid + 8) * Dd + d0 + 8];
    }

    // ldmatrix per-lane base: sel = lane>>3 picks (row-group, col-half)
    const int sel  = lane >> 3;
    const int lrow = ((sel >> 1) & 1) * 8 + (lane & 7);   // 0..15
    const int lcol = (sel & 1) * 8;                        // 0 or 8
    const uint32_t kh_base = smem_u32(&Ksh[lrow][lcol]);
    const uint32_t kl_base = smem_u32(&Ksl[lrow][lcol]);
    const uint32_t vh_base = smem_u32(&Vsh[lrow][lcol]);
    const uint32_t vl_base = smem_u32(&Vsl[lrow][lcol]);
    // offsets: jj -> +16 rows = 16*144B = 2304; kc -> +16 cols = 32B

    float o[8][4];
    #pragma unroll
    for (int j = 0; j < 8; ++j)
        #pragma unroll
        for (int k = 0; k < 4; ++k)
            o[j][k] = 0.f;
    float m0 = -1e30f, m1 = -1e30f, l0 = 0.f, l1 = 0.f;

    const int ld_r  = tid >> 3;           // 0..15
    const int ld_c  = (tid & 7) * 8;      // 0..56

    #pragma unroll 1
    for (int t0 = 0; t0 < Nn; t0 += 64) {
        __syncthreads();
        #pragma unroll
        for (int i = 0; i < 4; ++i) {
            const int r = ld_r + i * 16;
            *(uint4*)&Ksh[r][ld_c] = *(const uint4*)&Khg[(size_t)(t0 + r) * Dd + ld_c];
            *(uint4*)&Ksl[r][ld_c] = *(const uint4*)&Klg[(size_t)(t0 + r) * Dd + ld_c];
            *(uint4*)&Vsh[r][ld_c] = *(const uint4*)&Vhg[(size_t)r * Nn + t0 + ld_c];
            *(uint4*)&Vsl[r][ld_c] = *(const uint4*)&Vlg[(size_t)r * Nn + t0 + ld_c];
        }
        __syncthreads();

        // ---- S = Q K^T (3 passes, ldmatrix K frags) ----
        float s[8][4];
        #pragma unroll
        for (int j = 0; j < 8; ++j)
            #pragma unroll
            for (int k = 0; k < 4; ++k)
                s[j][k] = 0.f;
        #pragma unroll
        for (int jj = 0; jj < 4; ++jj) {
            #pragma unroll
            for (int kc = 0; kc < 4; ++kc) {
                const uint32_t off = (uint32_t)(jj * 2304 + kc * 32);
                uint32_t bh4[4], bl4[4];
                LDMX4(bh4, kh_base + off);
                LDMX4(bl4, kl_base + off);
                mma_bf16(s[2 * jj],     qh[kc], bh4);
                mma_bf16(s[2 * jj],     qh[kc], bl4);
                mma_bf16(s[2 * jj],     ql[kc], bh4);
                mma_bf16(s[2 * jj + 1], qh[kc], bh4 + 2);
                mma_bf16(s[2 * jj + 1], qh[kc], bl4 + 2);
                mma_bf16(s[2 * jj + 1], ql[kc], bh4 + 2);
            }
        }

        // ---- online softmax (MUFU exp) ----
        float mloc0 = -1e30f, mloc1 = -1e30f;
        #pragma unroll
        for (int j = 0; j < 8; ++j) {
            mloc0 = fmaxf(mloc0, fmaxf(s[j][0], s[j][1]));
            mloc1 = fmaxf(mloc1, fmaxf(s[j][2], s[j][3]));
        }
        mloc0 = fmaxf(mloc0, __shfl_xor_sync(0xffffffffu, mloc0, 1));
        mloc0 = fmaxf(mloc0, __shfl_xor_sync(0xffffffffu, mloc0, 2));
        mloc1 = fmaxf(mloc1, __shfl_xor_sync(0xffffffffu, mloc1, 1));
        mloc1 = fmaxf(mloc1, __shfl_xor_sync(0xffffffffu, mloc1, 2));
        const float mnew0 = fmaxf(m0, mloc0);
        const float mnew1 = fmaxf(m1, mloc1);
        const float corr0 = __expf(m0 - mnew0);
        const float corr1 = __expf(m1 - mnew1);
        #pragma unroll
        for (int j = 0; j < 8; ++j) {
            o[j][0] *= corr0; o[j][1] *= corr0;
            o[j][2] *= corr1; o[j][3] *= corr1;
        }
        float ls0 = 0.f, ls1 = 0.f;
        #pragma unroll
        for (int j = 0; j < 8; ++j) {
            s[j][0] = __expf(s[j][0] - mnew0);
            s[j][1] = __expf(s[j][1] - mnew0);
            s[j][2] = __expf(s[j][2] - mnew1);
            s[j][3] = __expf(s[j][3] - mnew1);
            ls0 += s[j][0] + s[j][1];
            ls1 += s[j][2] + s[j][3];
        }
        ls0 += __shfl_xor_sync(0xffffffffu, ls0, 1);
        ls0 += __shfl_xor_sync(0xffffffffu, ls0, 2);
        ls1 += __shfl_xor_sync(0xffffffffu, ls1, 1);
        ls1 += __shfl_xor_sync(0xffffffffu, ls1, 2);
        l0 = l0 * corr0 + ls0;
        l1 = l1 * corr1 + ls1;
        m0 = mnew0; m1 = mnew1;

        // ---- P -> bf16 hi/lo A-fragments ----
        uint32_t ph[4][4], pl[4][4];
        #pragma unroll
        for (int kc = 0; kc < 4; ++kc) {
            split2(s[2 * kc][0],     s[2 * kc][1],     ph[kc][0], pl[kc][0]);
            split2(s[2 * kc][2],     s[2 * kc][3],     ph[kc][1], pl[kc][1]);
            split2(s[2 * kc + 1][0], s[2 * kc + 1][1], ph[kc][2], pl[kc][2]);
            split2(s[2 * kc + 1][2], s[2 * kc + 1][3], ph[kc][3], pl[kc][3]);
        }

        // ---- O += P V (3 passes, ldmatrix V frags) ----
        #pragma unroll
        for (int jj = 0; jj < 4; ++jj) {
            #pragma unroll
            for (int kc = 0; kc < 4; ++kc) {
                const uint32_t off = (uint32_t)(jj * 2304 + kc * 32);
                uint32_t bh4[4], bl4[4];
                LDMX4(bh4, vh_base + off);
                LDMX4(bl4, vl_base + off);
                mma_bf16(o[2 * jj],     ph[kc], bh4);
                mma_bf16(o[2 * jj],     ph[kc], bl4);
                mma_bf16(o[2 * jj],     pl[kc], bh4);
                mma_bf16(o[2 * jj + 1], ph[kc], bh4 + 2);
                mma_bf16(o[2 * jj + 1], ph[kc], bl4 + 2);
                mma_bf16(o[2 * jj + 1], pl[kc], bh4 + 2);
            }
        }
    }

    // ---- write ctx [B,N,E] fp32 (R10-proven) ----
    const float inv0 = 1.f / l0;
    const float inv1 = 1.f / l1;
    const int b  = bh >> 4;
    const int hh = bh & 15;
    const int row0 = qrow0 + gid;
    #pragma unroll
    for (int j = 0; j < 8; ++j) {
        const int col = hh * Dd + j * 8 + 2 * tig;
        float2 o0 = {o[j][0] * inv0, o[j][1] * inv0};
        float2 o1 = {o[j][2] * inv1, o[j][3] * inv1};
        *(float2*)&g_ctx[(size_t)(b * Nn + row0) * Ee + col] = o0;
        *(float2*)&g_ctx[(size_t)(b * Nn + row0 + 8) * Ee + col] = o1;
    }
}

// ---------------------------------------------------------------------------
extern "C" void kernel_launch(void* const* d_in, const int* in_sizes, int n_in,
                              void* d_out, int out_size)
{
    const float* x      = (const float*)d_in[0];
    const float* w_qkv  = (const float*)d_in[1];
    const float* b_qkv  = (const float*)d_in[2];
    const float* w_proj = (const float*)d_in[3];
    const float* b_proj = (const float*)d_in[4];
    float* out = (float*)d_out;

    conv_wT_kernel<3 * Ee, 0><<<dim3(3 * Ee / 32, Ee / 32), 256>>>(w_qkv);
    conv_wT_kernel<Ee, 1><<<dim3(Ee / 32, Ee / 32), 256>>>(w_proj);
    hmma_gemm<3 * Ee, 0><<<dim3(3 * Ee / 128, ROWS / 128), 256>>>(x, b_qkv, nullptr);
    attn_kernel<<<dim3(Nn / 64, BH), 128>>>();
    hmma_gemm<Ee, 1><<<dim3(Ee / 128, ROWS / 128), 256>>>(nullptr, b_proj, out);
}

// round 14
// speedup vs baseline: 1.1525x; 1.0866x over previous
#include <cuda_runtime.h>
#include <cuda_bf16.h>
#include <cstdint>

#define Bb 2
#define Nn 2048
#define Ee 1024
#define Hh 16
#define Dd 64
#define BH (Bb*Hh)
#define ROWS (Bb*Nn)

// ---------------------------------------------------------------------------
// Scratch — ONLY ever referenced from device code (never passed as kernel args)
// ---------------------------------------------------------------------------
__device__ __nv_bfloat16 g_Qh[BH * Nn * Dd];   // [B,H,N,D], pre-scaled by 1/8
__device__ __nv_bfloat16 g_Ql[BH * Nn * Dd];
__device__ __nv_bfloat16 g_Kh[BH * Nn * Dd];
__device__ __nv_bfloat16 g_Kl[BH * Nn * Dd];
__device__ __nv_bfloat16 g_Vth[BH * Dd * Nn];  // [B,H,D,N] (transposed)
__device__ __nv_bfloat16 g_Vtl[BH * Dd * Nn];
__device__ float g_ctx[ROWS * Ee];             // attention out, [B,N,E] fp32
__device__ __nv_bfloat16 g_wqkvT_h[3 * Ee * Ee];  // [3E][E] (n-major)
__device__ __nv_bfloat16 g_wqkvT_l[3 * Ee * Ee];
__device__ __nv_bfloat16 g_wprojT_h[Ee * Ee];
__device__ __nv_bfloat16 g_wprojT_l[Ee * Ee];

// ---------------------------------------------------------------------------
// helpers
// ---------------------------------------------------------------------------
__device__ __forceinline__ uint32_t smem_u32(const void* p) {
    uint32_t a;
    asm("{ .reg .u64 t; cvta.to.shared.u64 t, %1; cvt.u32.u64 %0, t; }" : "=r"(a) : "l"(p));
    return a;
}

__device__ __forceinline__ void mma_bf16(float* c, const uint32_t* a, const uint32_t* b) {
    asm volatile(
        "mma.sync.aligned.m16n8k16.row.col.f32.bf16.bf16.f32 "
        "{%0,%1,%2,%3}, {%4,%5,%6,%7}, {%8,%9}, {%0,%1,%2,%3};"
        : "+f"(c[0]), "+f"(c[1]), "+f"(c[2]), "+f"(c[3])
        : "r"(a[0]), "r"(a[1]), "r"(a[2]), "r"(a[3]), "r"(b[0]), "r"(b[1]));
}

#define LDMX4(r, addr) \
    asm volatile("ldmatrix.sync.aligned.m8n8.x4.shared.b16 {%0,%1,%2,%3}, [%4];" \
        : "=r"((r)[0]), "=r"((r)[1]), "=r"((r)[2]), "=r"((r)[3]) : "r"(addr))

// fast split: packed bf16x2 hi + residual lo
__device__ __forceinline__ void split2(float x, float y, uint32_t& hi, uint32_t& lo) {
    __nv_bfloat162 h2 = __float22bfloat162_rn(make_float2(x, y));
    hi = *(uint32_t*)&h2;
    const float hx = __uint_as_float(hi << 16);
    const float hy = __uint_as_float(hi & 0xffff0000u);
    __nv_bfloat162 l2 = __float22bfloat162_rn(make_float2(x - hx, y - hy));
    lo = *(uint32_t*)&l2;
}

// ---------------------------------------------------------------------------
// Transpose + split W[1024, NW] -> device-global WT hi/lo [NW][1024] (R10-proven)
// ---------------------------------------------------------------------------
template<int NW, int MODE>
__global__ __launch_bounds__(256)
void conv_wT_kernel(const float* __restrict__ W) {
    __nv_bfloat16* Th = (MODE == 0) ? g_wqkvT_h : g_wprojT_h;
    __nv_bfloat16* Tl = (MODE == 0) ? g_wqkvT_l : g_wprojT_l;
    __shared__ float ts[32][33];
    const int tx = threadIdx.x & 31;
    const int ty = threadIdx.x >> 5;
    const int nb = blockIdx.x * 32;
    const int kb = blockIdx.y * 32;
    #pragma unroll
    for (int i = 0; i < 32; i += 8)
        ts[ty + i][tx] = W[(size_t)(kb + ty + i) * NW + nb + tx];
    __syncthreads();
    #pragma unroll
    for (int i = 0; i < 32; i += 8) {
        const float v = ts[tx][ty + i];
        const __nv_bfloat16 h = __float2bfloat16(v);
        Th[(size_t)(nb + ty + i) * Ee + kb + tx] = h;
        Tl[(size_t)(nb + ty + i) * Ee + kb + tx] = __float2bfloat16(v - __bfloat162float(h));
    }
}

// ---------------------------------------------------------------------------
// HMMA GEMM (R10-proven, verbatim)
// ---------------------------------------------------------------------------
template<int NW, int MODE>
__global__ __launch_bounds__(256)
void hmma_gemm(const float* __restrict__ Ain,
               const float* __restrict__ bias, float* __restrict__ Cout)
{
    __shared__ __nv_bfloat16 Ah[128][24], Al[128][24];
    __shared__ __nv_bfloat16 Bh[128][24], Bl[128][24];   // [n][k]

    const int tid  = threadIdx.x;
    const int lane = tid & 31;
    const int wid  = tid >> 5;
    const int gid  = lane >> 2;
    const int tig  = lane & 3;
    const int wm   = wid & 1;
    const int wn   = wid >> 1;

    const int m0 = blockIdx.y * 128;
    const int n0 = blockIdx.x * 128;

    const float* A = (MODE == 0) ? Ain : g_ctx;
    const __nv_bfloat16* WTh = (MODE == 0) ? g_wqkvT_h : g_wprojT_h;
    const __nv_bfloat16* WTl = (MODE == 0) ? g_wqkvT_l : g_wprojT_l;

    const int a_row = tid >> 1;
    const int a_k   = (tid & 1) * 8;

    float acc[4][4][4] = {};

    #pragma unroll 1
    for (int c = 0; c < 64; ++c) {
        const int k0 = c * 16;
        const float4 pa0 = *(const float4*)&A[(size_t)(m0 + a_row) * Ee + k0 + a_k];
        const float4 pa1 = *(const float4*)&A[(size_t)(m0 + a_row) * Ee + k0 + a_k + 4];
        const uint4  pbh = *(const uint4*)&WTh[(size_t)(n0 + a_row) * Ee + k0 + a_k];
        const uint4  pbl = *(const uint4*)&WTl[(size_t)(n0 + a_row) * Ee + k0 + a_k];

        __syncthreads();

        {
            const float va[8] = {pa0.x, pa0.y, pa0.z, pa0.w, pa1.x, pa1.y, pa1.z, pa1.w};
            __nv_bfloat16 h[8], l[8];
            #pragma unroll
            for (int j = 0; j < 8; ++j) {
                h[j] = __float2bfloat16(va[j]);
                l[j] = __float2bfloat16(va[j] - __bfloat162float(h[j]));
            }
            *(uint4*)&Ah[a_row][a_k] = *(uint4*)h;
            *(uint4*)&Al[a_row][a_k] = *(uint4*)l;
            *(uint4*)&Bh[a_row][a_k] = pbh;
            *(uint4*)&Bl[a_row][a_k] = pbl;
        }
        __syncthreads();

        uint32_t af[4][4], bhf[4][2], blf[4][2];
        #pragma unroll
        for (int mt = 0; mt < 4; ++mt) {
            const int r = wm * 64 + mt * 16 + gid;
            af[mt][0] = *(const uint32_t*)&Ah[r][2 * tig];
            af[mt][1] = *(const uint32_t*)&Ah[r + 8][2 * tig];
            af[mt][2] = *(const uint32_t*)&Ah[r][2 * tig + 8];
            af[mt][3] = *(const uint32_t*)&Ah[r + 8][2 * tig + 8];
        }
        #pragma unroll
        for (int nt = 0; nt < 4; ++nt) {
            const int rn = wn * 32 + nt * 8 + gid;
            bhf[nt][0] = *(const uint32_t*)&Bh[rn][2 * tig];
            bhf[nt][1] = *(const uint32_t*)&Bh[rn][2 * tig + 8];
            blf[nt][0] = *(const uint32_t*)&Bl[rn][2 * tig];
            blf[nt][1] = *(const uint32_t*)&Bl[rn][2 * tig + 8];
        }
        #pragma unroll
        for (int mt = 0; mt < 4; ++mt)
            #pragma unroll
            for (int nt = 0; nt < 4; ++nt)
                mma_bf16(acc[mt][nt], af[mt], bhf[nt]);
        #pragma unroll
        for (int mt = 0; mt < 4; ++mt)
            #pragma unroll
            for (int nt = 0; nt < 4; ++nt)
                mma_bf16(acc[mt][nt], af[mt], blf[nt]);
        #pragma unroll
        for (int mt = 0; mt < 4; ++mt) {
            const int r = wm * 64 + mt * 16 + gid;
            af[mt][0] = *(const uint32_t*)&Al[r][2 * tig];
            af[mt][1] = *(const uint32_t*)&Al[r + 8][2 * tig];
            af[mt][2] = *(const uint32_t*)&Al[r][2 * tig + 8];
            af[mt][3] = *(const uint32_t*)&Al[r + 8][2 * tig + 8];
        }
        #pragma unroll
        for (int mt = 0; mt < 4; ++mt)
            #pragma unroll
            for (int nt = 0; nt < 4; ++nt)
                mma_bf16(acc[mt][nt], af[mt], bhf[nt]);
    }

    #pragma unroll
    for (int mt = 0; mt < 4; ++mt) {
        #pragma unroll
        for (int hrow = 0; hrow < 2; ++hrow) {
            const int m = m0 + wm * 64 + mt * 16 + hrow * 8 + gid;
            #pragma unroll
            for (int nt = 0; nt < 4; ++nt) {
                const int c0 = n0 + wn * 32 + nt * 8 + tig * 2;
                const float r0 = acc[mt][nt][hrow * 2 + 0] + bias[c0];
                const float r1 = acc[mt][nt][hrow * 2 + 1] + bias[c0 + 1];
                if (MODE == 0) {
                    const int sel = c0 >> 10;
                    const int rem = c0 & 1023;
                    const int hh  = rem >> 6;
                    const int d0  = rem & 63;
                    const int b   = m >> 11;
                    const int n   = m & 2047;
                    if (sel == 2) {
                        const size_t vidx = ((size_t)(b * Hh + hh) * Dd + d0) * Nn + n;
                        const __nv_bfloat16 h0 = __float2bfloat16(r0);
                        const __nv_bfloat16 h1 = __float2bfloat16(r1);
                        g_Vth[vidx]      = h0;
                        g_Vtl[vidx]      = __float2bfloat16(r0 - __bfloat162float(h0));
                        g_Vth[vidx + Nn] = h1;
                        g_Vtl[vidx + Nn] = __float2bfloat16(r1 - __bfloat162float(h1));
                    } else {
                        const size_t idx = ((size_t)(b * Hh + hh) * Nn + n) * Dd + d0;
                        const float s0 = (sel == 0) ? r0 * 0.125f : r0;
                        const float s1 = (sel == 0) ? r1 * 0.125f : r1;
                        uint32_t hi, lo;
                        split2(s0, s1, hi, lo);
                        __nv_bfloat16* dh = (sel == 0) ? g_Qh : g_Kh;
                        __nv_bfloat16* dl = (sel == 0) ? g_Ql : g_Kl;
                        *(uint32_t*)&dh[idx] = hi;
                        *(uint32_t*)&dl[idx] = lo;
                    }
                } else {
                    float2 o = {r0, r1};
                    *(float2*)&Cout[(size_t)m * NW + c0] = o;
                }
            }
        }
    }
}

// ---------------------------------------------------------------------------
// HMMA flash attention — R13 body (ldmatrix + MUFU exp + fast split), with
// __launch_bounds__(128, 3) to force regs <= 168 so 3 CTAs/SM fit again.
// grid (Nn/64, BH), 128 threads.
// ---------------------------------------------------------------------------
__global__ __launch_bounds__(128, 3)
void attn_kernel()
{
    __shared__ __nv_bfloat16 Ksh[64][72], Ksl[64][72];
    __shared__ __nv_bfloat16 Vsh[64][72], Vsl[64][72];   // [d][kv]

    const int tid  = threadIdx.x;
    const int lane = tid & 31;
    const int w    = tid >> 5;            // 0..3
    const int gid  = lane >> 2;
    const int tig  = lane & 3;

    const int bh    = blockIdx.y;
    const int qrow0 = blockIdx.x * 64 + w * 16;

    const __nv_bfloat16* Qhp = g_Qh + ((size_t)bh * Nn + qrow0) * Dd;
    const __nv_bfloat16* Qlp = g_Ql + ((size_t)bh * Nn + qrow0) * Dd;
    const __nv_bfloat16* Khg = g_Kh + (size_t)bh * Nn * Dd;
    const __nv_bfloat16* Klg = g_Kl + (size_t)bh * Nn * Dd;
    const __nv_bfloat16* Vhg = g_Vth + (size_t)bh * Dd * Nn;
    const __nv_bfloat16* Vlg = g_Vtl + (size_t)bh * Dd * Nn;

    uint32_t qh[4][4], ql[4][4];
    #pragma unroll
    for (int kc = 0; kc < 4; ++kc) {
        const int d0 = kc * 16 + 2 * tig;
        qh[kc][0] = *(const uint32_t*)&Qhp[(size_t)gid * Dd + d0];
        qh[kc][1] = *(const uint32_t*)&Qhp[(size_t)(gid + 8) * Dd + d0];
        qh[kc][2] = *(const uint32_t*)&Qhp[(size_t)gid * Dd + d0 + 8];
        qh[kc][3] = *(const uint32_t*)&Qhp[(size_t)(gid + 8) * Dd + d0 + 8];
        ql[kc][0] = *(const uint32_t*)&Qlp[(size_t)gid * Dd + d0];
        ql[kc][1] = *(const uint32_t*)&Qlp[(size_t)(gid + 8) * Dd + d0];
        ql[kc][2] = *(const uint32_t*)&Qlp[(size_t)gid * Dd + d0 + 8];
        ql[kc][3] = *(const uint32_t*)&Qlp[(size_t)(gid + 8) * Dd + d0 + 8];
    }

    // ldmatrix per-lane base: sel = lane>>3 picks (row-group, col-half)
    const int sel  = lane >> 3;
    const int lrow = ((sel >> 1) & 1) * 8 + (lane & 7);   // 0..15
    const int lcol = (sel & 1) * 8;                        // 0 or 8
    const uint32_t kh_base = smem_u32(&Ksh[lrow][lcol]);
    const uint32_t kl_base = smem_u32(&Ksl[lrow][lcol]);
    const uint32_t vh_base = smem_u32(&Vsh[lrow][lcol]);
    const uint32_t vl_base = smem_u32(&Vsl[lrow][lcol]);
    // offsets: jj -> +16 rows = 16*144B = 2304; kc -> +16 cols = 32B

    float o[8][4];
    #pragma unroll
    for (int j = 0; j < 8; ++j)
        #pragma unroll
        for (int k = 0; k < 4; ++k)
            o[j][k] = 0.f;
    float m0 = -1e30f, m1 = -1e30f, l0 = 0.f, l1 = 0.f;

    const int ld_r  = tid >> 3;           // 0..15
    const int ld_c  = (tid & 7) * 8;      // 0..56

    #pragma unroll 1
    for (int t0 = 0; t0 < Nn; t0 += 64) {
        __syncthreads();
        #pragma unroll
        for (int i = 0; i < 4; ++i) {
            const int r = ld_r + i * 16;
            *(uint4*)&Ksh[r][ld_c] = *(const uint4*)&Khg[(size_t)(t0 + r) * Dd + ld_c];
            *(uint4*)&Ksl[r][ld_c] = *(const uint4*)&Klg[(size_t)(t0 + r) * Dd + ld_c];
            *(uint4*)&Vsh[r][ld_c] = *(const uint4*)&Vhg[(size_t)r * Nn + t0 + ld_c];
            *(uint4*)&Vsl[r][ld_c] = *(const uint4*)&Vlg[(size_t)r * Nn + t0 + ld_c];
        }
        __syncthreads();

        // ---- S = Q K^T (3 passes, ldmatrix K frags) ----
        float s[8][4];
        #pragma unroll
        for (int j = 0; j < 8; ++j)
            #pragma unroll
            for (int k = 0; k < 4; ++k)
                s[j][k] = 0.f;
        #pragma unroll
        for (int jj = 0; jj < 4; ++jj) {
            #pragma unroll
            for (int kc = 0; kc < 4; ++kc) {
                const uint32_t off = (uint32_t)(jj * 2304 + kc * 32);
                uint32_t bh4[4], bl4[4];
                LDMX4(bh4, kh_base + off);
                LDMX4(bl4, kl_base + off);
                mma_bf16(s[2 * jj],     qh[kc], bh4);
                mma_bf16(s[2 * jj],     qh[kc], bl4);
                mma_bf16(s[2 * jj],     ql[kc], bh4);
                mma_bf16(s[2 * jj + 1], qh[kc], bh4 + 2);
                mma_bf16(s[2 * jj + 1], qh[kc], bl4 + 2);
                mma_bf16(s[2 * jj + 1], ql[kc], bh4 + 2);
            }
        }

        // ---- online softmax (MUFU exp) ----
        float mloc0 = -1e30f, mloc1 = -1e30f;
        #pragma unroll
        for (int j = 0; j < 8; ++j) {
            mloc0 = fmaxf(mloc0, fmaxf(s[j][0], s[j][1]));
            mloc1 = fmaxf(mloc1, fmaxf(s[j][2], s[j][3]));
        }
        mloc0 = fmaxf(mloc0, __shfl_xor_sync(0xffffffffu, mloc0, 1));
        mloc0 = fmaxf(mloc0, __shfl_xor_sync(0xffffffffu, mloc0, 2));
        mloc1 = fmaxf(mloc1, __shfl_xor_sync(0xffffffffu, mloc1, 1));
        mloc1 = fmaxf(mloc1, __shfl_xor_sync(0xffffffffu, mloc1, 2));
        const float mnew0 = fmaxf(m0, mloc0);
        const float mnew1 = fmaxf(m1, mloc1);
        const float corr0 = __expf(m0 - mnew0);
        const float corr1 = __expf(m1 - mnew1);
        #pragma unroll
        for (int j = 0; j < 8; ++j) {
            o[j][0] *= corr0; o[j][1] *= corr0;
            o[j][2] *= corr1; o[j][3] *= corr1;
        }
        float ls0 = 0.f, ls1 = 0.f;
        #pragma unroll
        for (int j = 0; j < 8; ++j) {
            s[j][0] = __expf(s[j][0] - mnew0);
            s[j][1] = __expf(s[j][1] - mnew0);
            s[j][2] = __expf(s[j][2] - mnew1);
            s[j][3] = __expf(s[j][3] - mnew1);
            ls0 += s[j][0] + s[j][1];
            ls1 += s[j][2] + s[j][3];
        }
        ls0 += __shfl_xor_sync(0xffffffffu, ls0, 1);
        ls0 += __shfl_xor_sync(0xffffffffu, ls0, 2);
        ls1 += __shfl_xor_sync(0xffffffffu, ls1, 1);
        ls1 += __shfl_xor_sync(0xffffffffu, ls1, 2);
        l0 = l0 * corr0 + ls0;
        l1 = l1 * corr1 + ls1;
        m0 = mnew0; m1 = mnew1;

        // ---- P -> bf16 hi/lo A-fragments ----
        uint32_t ph[4][4], pl[4][4];
        #pragma unroll
        for (int kc = 0; kc < 4; ++kc) {
            split2(s[2 * kc][0],     s[2 * kc][1],     ph[kc][0], pl[kc][0]);
            split2(s[2 * kc][2],     s[2 * kc][3],     ph[kc][1], pl[kc][1]);
            split2(s[2 * kc + 1][0], s[2 * kc + 1][1], ph[kc][2], pl[kc][2]);
            split2(s[2 * kc + 1][2], s[2 * kc + 1][3], ph[kc][3], pl[kc][3]);
        }

        // ---- O += P V (3 passes, ldmatrix V frags) ----
        #pragma unroll
        for (int jj = 0; jj < 4; ++jj) {
            #pragma unroll
            for (int kc = 0; kc < 4; ++kc) {
                const uint32_t off = (uint32_t)(jj * 2304 + kc * 32);
                uint32_t bh4[4], bl4[4];
                LDMX4(bh4, vh_base + off);
                LDMX4(bl4, vl_base + off);
                mma_bf16(o[2 * jj],     ph[kc], bh4);
                mma_bf16(o[2 * jj],     ph[kc], bl4);
                mma_bf16(o[2 * jj],     pl[kc], bh4);
                mma_bf16(o[2 * jj + 1], ph[kc], bh4 + 2);
                mma_bf16(o[2 * jj + 1], ph[kc], bl4 + 2);
                mma_bf16(o[2 * jj + 1], pl[kc], bh4 + 2);
            }
        }
    }

    // ---- write ctx [B,N,E] fp32 (R10-proven) ----
    const float inv0 = 1.f / l0;
    const float inv1 = 1.f / l1;
    const int b  = bh >> 4;
    const int hh = bh & 15;
    const int row0 = qrow0 + gid;
    #pragma unroll
    for (int j = 0; j < 8; ++j) {
        const int col = hh * Dd + j * 8 + 2 * tig;
        float2 o0 = {o[j][0] * inv0, o[j][1] * inv0};
        float2 o1 = {o[j][2] * inv1, o[j][3] * inv1};
        *(float2*)&g_ctx[(size_t)(b * Nn + row0) * Ee + col] = o0;
        *(float2*)&g_ctx[(size_t)(b * Nn + row0 + 8) * Ee + col] = o1;
    }
}

// ---------------------------------------------------------------------------
extern "C" void kernel_launch(void* const* d_in, const int* in_sizes, int n_in,
                              void* d_out, int out_size)
{
    const float* x      = (const float*)d_in[0];
    const float* w_qkv  = (const float*)d_in[1];
    const float* b_qkv  = (const float*)d_in[2];
    const float* w_proj = (const float*)d_in[3];
    const float* b_proj = (const float*)d_in[4];
    float* out = (float*)d_out;

    conv_wT_kernel<3 * Ee, 0><<<dim3(3 * Ee / 32, Ee / 32), 256>>>(w_qkv);
    conv_wT_kernel<Ee, 1><<<dim3(Ee / 32, Ee / 32), 256>>>(w_proj);
    hmma_gemm<3 * Ee, 0><<<dim3(3 * Ee / 128, ROWS / 128), 256>>>(x, b_qkv, nullptr);
    attn_kernel<<<dim3(Nn / 64, BH), 128>>>();
    hmma_gemm<Ee, 1><<<dim3(Ee / 128, ROWS / 128), 256>>>(nullptr, b_proj, out);
}